// round 15
// baseline (speedup 1.0000x reference)
#include <cuda_runtime.h>
#include <cuda_fp16.h>

// x:   (B=4, 3, H=2048, W=2048) fp32
// LUT: (3, 33, 33, 33) fp32, index = c*33^3 + b*1089 + g*33 + r
//
// Champion formulation (R5 structure + R7 prefetch + R8/R9 micro + R14 prologue):
//  - 3-way channel split: 50 blocks per output channel, each block builds a
//    single-channel fp16 r-pair table (143.7 KB smem) => 4 LDS.32 gathers/px.
//  - Lockstep strides across channel groups => x read ~once via L2 sharing.
//  - Software-pipelined x prefetch hides LDG latency under LDS phases.
//  - Two-pass table build: each LUT value fetched from global exactly once.
// Measured: ~110 us, L1TEX (smem crossbar) ~90% busy = binding resource.
#define NPTS   35937            // 33^3
#define ROW    33
#define PLANE  1089
#define HW4    1048576          // 2048*2048/4
#define NVEC   4194304          // B*HW/4 float4 pixel-vecs per plane set
#define THREADS 1024
#define GROUPS  50              // blocks per channel group
#define BLOCKS  (3 * GROUPS)    // 150
#define SMEM_BYTES (NPTS * 4 + 16)   // half2 pair table for ONE channel

extern __shared__ unsigned char smem_raw[];

struct Gather { __half2 p00, p10, p01, p11; float fr, fg, fb; };

// Stage 1: compute indices and issue the 4 LDS.32 gathers for one pixel.
// x guaranteed in [0,1) => lattice coords in [0,32) => no clamping needed.
__device__ __forceinline__ Gather gather_px(float r, float g, float b,
                                            const __half2* __restrict__ P) {
    float rr = r * 32.0f;
    float gg = g * 32.0f;
    float bb = b * 32.0f;
    float rf = floorf(rr);
    float gf = floorf(gg);
    float bf = floorf(bb);
    Gather G;
    G.fr = rr - rf;
    G.fg = gg - gf;
    G.fb = bb - bf;
    int i00 = (int)bf * PLANE + (int)gf * ROW + (int)rf;
    G.p00 = P[i00];
    G.p10 = P[i00 + ROW];
    G.p01 = P[i00 + PLANE];
    G.p11 = P[i00 + PLANE + ROW];
    return G;
}

// Stage 2: pure math, no memory.
__device__ __forceinline__ float lerp_px(const Gather& G) {
    float2 p00 = __half22float2(G.p00);
    float2 p10 = __half22float2(G.p10);
    float2 p01 = __half22float2(G.p01);
    float2 p11 = __half22float2(G.p11);

    float v00 = fmaf(G.fr, p00.y - p00.x, p00.x);
    float v10 = fmaf(G.fr, p10.y - p10.x, p10.x);
    float v01 = fmaf(G.fr, p01.y - p01.x, p01.x);
    float v11 = fmaf(G.fr, p11.y - p11.x, p11.x);

    float v0 = fmaf(G.fg, v10 - v00, v00);
    float v1 = fmaf(G.fg, v11 - v01, v01);
    return fmaf(G.fb, v1 - v0, v0);
}

__global__ void __launch_bounds__(THREADS, 1)
lut3d_chsplit_kernel(const float* __restrict__ x, const float* __restrict__ LUT,
                     float* __restrict__ out) {
    __half2* P = (__half2*)smem_raw;
    __half*  Ph = (__half*)smem_raw;        // 16-bit view of the same table

    const int c    = blockIdx.x % 3;        // output channel this block computes
    const int rank = blockIdx.x / 3;        // 0..GROUPS-1, identical across channels

    // Two-pass build of the r-pair table P[i] = {LUT[c,i], LUT[c,i+1]} (fp16).
    // Pass 1: fetch each LUT value exactly once (single coalesced LDG stream),
    //         store as lo-half of its own entry.
    const float* Lc = LUT + c * NPTS;
    for (int i = threadIdx.x; i < NPTS; i += THREADS) {
        Ph[2 * i] = __float2half_rn(__ldg(&Lc[i]));
    }
    __syncthreads();
    // Pass 2: fill hi-half from neighbor's lo-half via smem. Reads (P[i+1].lo)
    // and writes (P[i].hi) are disjoint 16-bit locations -> race-free.
    for (int i = threadIdx.x; i < NPTS; i += THREADS) {
        int j = (i + 1 < NPTS) ? i + 1 : i;
        __half t = Ph[2 * j];
        Ph[2 * i + 1] = t;
    }
    __syncthreads();

    const float4* __restrict__ x4 = (const float4*)x;
    float4* __restrict__ op = (float4*)out + c * HW4;   // this channel's out plane

    const int stride = GROUPS * THREADS;    // same stride for every channel group

    int v = rank * THREADS + threadIdx.x;
    if (v >= NVEC) return;

    // base(v) = img*3*HW4 + iv = v + img*2*HW4, img = v >> 20
    int base = v + ((v >> 20) << 21);

    // Prologue: load first iteration's pixel vectors.
    float4 pr = x4[base];
    float4 pg = x4[base + HW4];
    float4 pb = x4[base + 2 * HW4];

    while (true) {
        int vn = v + stride;
        bool more = (vn < NVEC);

        // Prefetch next iteration's x while current gathers run.
        int vc = min(vn, NVEC - 1);
        int base_n = vc + ((vc >> 20) << 21);
        float4 nr = x4[base_n];
        float4 ng = x4[base_n + HW4];
        float4 nb = x4[base_n + 2 * HW4];

        // Phase 1: issue ALL 16 gathers back-to-back (max crossbar occupancy).
        Gather g0 = gather_px(pr.x, pg.x, pb.x, P);
        Gather g1 = gather_px(pr.y, pg.y, pb.y, P);
        Gather g2 = gather_px(pr.z, pg.z, pb.z, P);
        Gather g3 = gather_px(pr.w, pg.w, pb.w, P);

        // Phase 2: pure math.
        float4 o;
        o.x = lerp_px(g0);
        o.y = lerp_px(g1);
        o.z = lerp_px(g2);
        o.w = lerp_px(g3);

        op[base] = o;

        if (!more) break;
        v = vn;
        base = base_n;
        pr = nr; pg = ng; pb = nb;
    }
}

extern "C" void kernel_launch(void* const* d_in, const int* in_sizes, int n_in,
                              void* d_out, int out_size) {
    const float* x   = (const float*)d_in[0];
    const float* LUT = (const float*)d_in[1];
    float* out = (float*)d_out;

    cudaFuncSetAttribute(lut3d_chsplit_kernel,
                         cudaFuncAttributeMaxDynamicSharedMemorySize, SMEM_BYTES);
    lut3d_chsplit_kernel<<<BLOCKS, THREADS, SMEM_BYTES>>>(x, LUT, out);
}

// round 16
// speedup vs baseline: 1.0095x; 1.0095x over previous
#include <cuda_runtime.h>
#include <cuda_fp16.h>

// x:   (B=4, 3, H=2048, W=2048) fp32
// LUT: (3, 33, 33, 33) fp32, index = c*33^3 + b*1089 + g*33 + r
//
// FINAL champion (R5 structure + R7 prefetch + R8/R9 micro, locked at R10):
//  - 3-way channel split: 50 blocks per output channel, each block builds a
//    single-channel fp16 r-pair table (143.7 KB smem) => 4 LDS.32 gathers/px.
//  - Lockstep strides across channel groups => x read ~once via L2 sharing.
//  - Software-pipelined x prefetch hides LDG latency under LDS phases.
// Measured: 110.7 us stable; L1TEX (smem crossbar) ~90% busy = roofline.
#define NPTS   35937            // 33^3
#define ROW    33
#define PLANE  1089
#define HW4    1048576          // 2048*2048/4
#define NVEC   4194304          // B*HW/4 float4 pixel-vecs per plane set
#define THREADS 1024
#define GROUPS  50              // blocks per channel group
#define BLOCKS  (3 * GROUPS)    // 150
#define SMEM_BYTES (NPTS * 4 + 16)   // half2 pair table for ONE channel

extern __shared__ unsigned char smem_raw[];

struct Gather { __half2 p00, p10, p01, p11; float fr, fg, fb; };

// Stage 1: compute indices and issue the 4 LDS.32 gathers for one pixel.
// x guaranteed in [0,1) => lattice coords in [0,32) => no clamping needed.
__device__ __forceinline__ Gather gather_px(float r, float g, float b,
                                            const __half2* __restrict__ P) {
    float rr = r * 32.0f;
    float gg = g * 32.0f;
    float bb = b * 32.0f;
    float rf = floorf(rr);
    float gf = floorf(gg);
    float bf = floorf(bb);
    Gather G;
    G.fr = rr - rf;
    G.fg = gg - gf;
    G.fb = bb - bf;
    int i00 = (int)bf * PLANE + (int)gf * ROW + (int)rf;
    G.p00 = P[i00];
    G.p10 = P[i00 + ROW];
    G.p01 = P[i00 + PLANE];
    G.p11 = P[i00 + PLANE + ROW];
    return G;
}

// Stage 2: pure math, no memory.
__device__ __forceinline__ float lerp_px(const Gather& G) {
    float2 p00 = __half22float2(G.p00);
    float2 p10 = __half22float2(G.p10);
    float2 p01 = __half22float2(G.p01);
    float2 p11 = __half22float2(G.p11);

    float v00 = fmaf(G.fr, p00.y - p00.x, p00.x);
    float v10 = fmaf(G.fr, p10.y - p10.x, p10.x);
    float v01 = fmaf(G.fr, p01.y - p01.x, p01.x);
    float v11 = fmaf(G.fr, p11.y - p11.x, p11.x);

    float v0 = fmaf(G.fg, v10 - v00, v00);
    float v1 = fmaf(G.fg, v11 - v01, v01);
    return fmaf(G.fb, v1 - v0, v0);
}

__global__ void __launch_bounds__(THREADS, 1)
lut3d_chsplit_kernel(const float* __restrict__ x, const float* __restrict__ LUT,
                     float* __restrict__ out) {
    __half2* P = (__half2*)smem_raw;

    const int c    = blockIdx.x % 3;        // output channel this block computes
    const int rank = blockIdx.x / 3;        // 0..GROUPS-1, identical across channels

    // Build this channel's r-pair table: P[i] = {LUT[c,i], LUT[c,i+1]} (fp16).
    // Scalar loads: LUT + c*NPTS is only 4-byte aligned for c=1,2, so no float4.
    const float* Lc = LUT + c * NPTS;
    for (int i = threadIdx.x; i < NPTS; i += THREADS) {
        float v0 = __ldg(&Lc[i]);
        int j = (i + 1 < NPTS) ? i + 1 : i;
        float v1 = __ldg(&Lc[j]);
        P[i] = __floats2half2_rn(v0, v1);
    }
    __syncthreads();

    const float4* __restrict__ x4 = (const float4*)x;
    float4* __restrict__ op = (float4*)out + c * HW4;   // this channel's out plane

    const int stride = GROUPS * THREADS;    // same stride for every channel group

    int v = rank * THREADS + threadIdx.x;
    if (v >= NVEC) return;

    // base(v) = img*3*HW4 + iv = v + img*2*HW4, img = v >> 20
    int base = v + ((v >> 20) << 21);

    // Prologue: load first iteration's pixel vectors.
    float4 pr = x4[base];
    float4 pg = x4[base + HW4];
    float4 pb = x4[base + 2 * HW4];

    while (true) {
        int vn = v + stride;
        bool more = (vn < NVEC);

        // Prefetch next iteration's x while current gathers run.
        int vc = min(vn, NVEC - 1);
        int base_n = vc + ((vc >> 20) << 21);
        float4 nr = x4[base_n];
        float4 ng = x4[base_n + HW4];
        float4 nb = x4[base_n + 2 * HW4];

        // Phase 1: issue ALL 16 gathers back-to-back (max crossbar occupancy).
        Gather g0 = gather_px(pr.x, pg.x, pb.x, P);
        Gather g1 = gather_px(pr.y, pg.y, pb.y, P);
        Gather g2 = gather_px(pr.z, pg.z, pb.z, P);
        Gather g3 = gather_px(pr.w, pg.w, pb.w, P);

        // Phase 2: pure math.
        float4 o;
        o.x = lerp_px(g0);
        o.y = lerp_px(g1);
        o.z = lerp_px(g2);
        o.w = lerp_px(g3);

        op[base] = o;

        if (!more) break;
        v = vn;
        base = base_n;
        pr = nr; pg = ng; pb = nb;
    }
}

extern "C" void kernel_launch(void* const* d_in, const int* in_sizes, int n_in,
                              void* d_out, int out_size) {
    const float* x   = (const float*)d_in[0];
    const float* LUT = (const float*)d_in[1];
    float* out = (float*)d_out;

    cudaFuncSetAttribute(lut3d_chsplit_kernel,
                         cudaFuncAttributeMaxDynamicSharedMemorySize, SMEM_BYTES);
    lut3d_chsplit_kernel<<<BLOCKS, THREADS, SMEM_BYTES>>>(x, LUT, out);
}